// round 1
// baseline (speedup 1.0000x reference)
#include <cuda_runtime.h>

#define D 128
#define KNEIGH 25
#define NMAX 50000
#define ALPHA 0.2f
#define BN_EPS 1e-5f

__device__ float  g_x [NMAX * D];
__device__ float  g_zA[NMAX * D];
__device__ float  g_zB[NMAX * D];
__device__ float  g_Wc[D * D];
__device__ float  g_wsn[2 * D];
__device__ double g_stats[2 * D];
__device__ float  g_aff[2 * D];

__device__ __forceinline__ float lrelu(float v) { return v >= 0.f ? v : ALPHA * v; }

__global__ void prep_kernel(const float* __restrict__ W_t,
                            const float* __restrict__ W1,
                            const float* __restrict__ a_att) {
    if (blockIdx.x < D) {
        __shared__ float wrow[D];
        int d = blockIdx.x, j = threadIdx.x;
        wrow[j] = W_t[d * D + j];
        __syncthreads();
        float s = 0.f;
#pragma unroll 8
        for (int t = 0; t < D; t++) s = fmaf(wrow[t], W1[t * D + j], s);
        g_Wc[d * D + j] = s;
    } else {
        int d = threadIdx.x;
        float s0 = 0.f, s1 = 0.f;
        for (int t = 0; t < D; t++) {
            float w = W_t[d * D + t];
            s0 = fmaf(w, a_att[t], s0);
            s1 = fmaf(w, a_att[D + t], s1);
        }
        g_wsn[d]     = s0;
        g_wsn[D + d] = s1;
        g_stats[d] = 0.0;
        g_stats[D + d] = 0.0;
    }
}

__global__ void __launch_bounds__(128) attn_kernel(
    const float* __restrict__ self_vecs,
    const float* __restrict__ neigh,
    const float* __restrict__ eps_p,
    int N) {
    int warp = (int)((blockIdx.x * 128u + threadIdx.x) >> 5);
    int lane = threadIdx.x & 31;
    if (warp >= N) return;

    float4 ws = *(const float4*)&g_wsn[lane * 4];
    float4 wn = *(const float4*)&g_wsn[D + lane * 4];
    float4 sv = *(const float4*)&self_vecs[(size_t)warp * D + lane * 4];

    float4 v[KNEIGH];
    const float* np = neigh + (size_t)warp * KNEIGH * D + lane * 4;
#pragma unroll
    for (int k = 0; k < KNEIGH; k++)
        v[k] = *(const float4*)(np + (size_t)k * D);

    float ss = sv.x * ws.x + sv.y * ws.y + sv.z * ws.z + sv.w * ws.w;
#pragma unroll
    for (int o = 16; o > 0; o >>= 1) ss += __shfl_xor_sync(0xffffffffu, ss, o);

    float sc[KNEIGH];
#pragma unroll
    for (int k = 0; k < KNEIGH; k++) {
        float p = v[k].x * wn.x + v[k].y * wn.y + v[k].z * wn.z + v[k].w * wn.w;
#pragma unroll
        for (int o = 16; o > 0; o >>= 1) p += __shfl_xor_sync(0xffffffffu, p, o);
        p += ss;
        sc[k] = lrelu(p);
    }

    float mx = sc[0];
#pragma unroll
    for (int k = 1; k < KNEIGH; k++) mx = fmaxf(mx, sc[k]);
    float sum = 0.f;
#pragma unroll
    for (int k = 0; k < KNEIGH; k++) { sc[k] = __expf(sc[k] - mx); sum += sc[k]; }
    float inv = 1.f / sum;

    float4 acc = make_float4(0.f, 0.f, 0.f, 0.f);
#pragma unroll
    for (int k = 0; k < KNEIGH; k++) {
        float a = sc[k] * inv;
        acc.x = fmaf(a, v[k].x, acc.x);
        acc.y = fmaf(a, v[k].y, acc.y);
        acc.z = fmaf(a, v[k].z, acc.z);
        acc.w = fmaf(a, v[k].w, acc.w);
    }

    float e = 1.f + *eps_p;
    float4 o;
    o.x = fmaf(e, sv.x, acc.x);
    o.y = fmaf(e, sv.y, acc.y);
    o.z = fmaf(e, sv.z, acc.z);
    o.w = fmaf(e, sv.w, acc.w);
    *(float4*)&g_x[(size_t)warp * D + lane * 4] = o;
}

__global__ void __launch_bounds__(512) gemm_kernel(
    const float* __restrict__ X,
    const float* __restrict__ W,
    const float* __restrict__ bias,
    const float* __restrict__ aff,
    float* __restrict__ Z,
    int N) {
    extern __shared__ float smem[];
    float* wsm = smem;
    float* xsm = smem + 16384;

    int tid = threadIdx.x;
    int n0  = blockIdx.x * 128;

#pragma unroll
    for (int i = 0; i < 8; i++) {
        int f = tid + i * 512;
        *(float4*)&wsm[f * 4] = *(const float4*)&W[f * 4];
    }

    int row = tid & 127;
    int kb  = (tid >> 7) * 32;
    bool valid = (n0 + row) < N;
#pragma unroll
    for (int i = 0; i < 8; i++) {
        int k0 = kb + i * 4;
        float4 vv = make_float4(0.f, 0.f, 0.f, 0.f);
        if (valid) vv = *(const float4*)&X[(size_t)(n0 + row) * D + k0];
        if (aff) {
            float4 a = *(const float4*)&aff[k0];
            float4 b = *(const float4*)&aff[D + k0];
            vv.x = lrelu(fmaf(a.x, vv.x, b.x));
            vv.y = lrelu(fmaf(a.y, vv.y, b.y));
            vv.z = lrelu(fmaf(a.z, vv.z, b.z));
            vv.w = lrelu(fmaf(a.w, vv.w, b.w));
        }
        xsm[(k0 + 0) * 128 + row] = vv.x;
        xsm[(k0 + 1) * 128 + row] = vv.y;
        xsm[(k0 + 2) * 128 + row] = vv.z;
        xsm[(k0 + 3) * 128 + row] = vv.w;
    }
    __syncthreads();

    int ty = tid >> 5, tx = tid & 31;
    int r0 = ty * 8, c0 = tx * 4;
    float acc[8][4] = {};

#pragma unroll 4
    for (int k = 0; k < 128; k++) {
        float4 wv = *(float4*)&wsm[k * 128 + c0];
        float4 x0 = *(float4*)&xsm[k * 128 + r0];
        float4 x1 = *(float4*)&xsm[k * 128 + r0 + 4];
        float xr[8] = {x0.x, x0.y, x0.z, x0.w, x1.x, x1.y, x1.z, x1.w};
#pragma unroll
        for (int r = 0; r < 8; r++) {
            acc[r][0] = fmaf(xr[r], wv.x, acc[r][0]);
            acc[r][1] = fmaf(xr[r], wv.y, acc[r][1]);
            acc[r][2] = fmaf(xr[r], wv.z, acc[r][2]);
            acc[r][3] = fmaf(xr[r], wv.w, acc[r][3]);
        }
    }

    float4 bv = *(const float4*)&bias[c0];
    float s1[4] = {0.f, 0.f, 0.f, 0.f};
    float s2[4] = {0.f, 0.f, 0.f, 0.f};
#pragma unroll
    for (int r = 0; r < 8; r++) {
        int n = n0 + r0 + r;
        if (n < N) {
            float4 o;
            o.x = acc[r][0] + bv.x;
            o.y = acc[r][1] + bv.y;
            o.z = acc[r][2] + bv.z;
            o.w = acc[r][3] + bv.w;
            *(float4*)&Z[(size_t)n * D + c0] = o;
            s1[0] += o.x; s2[0] += o.x * o.x;
            s1[1] += o.y; s2[1] += o.y * o.y;
            s1[2] += o.z; s2[2] += o.z * o.z;
            s1[3] += o.w; s2[3] += o.w * o.w;
        }
    }

    __syncthreads();
    float* red = smem;
    if (tid < 256) red[tid] = 0.f;
    __syncthreads();
#pragma unroll
    for (int c = 0; c < 4; c++) {
        atomicAdd(&red[c0 + c], s1[c]);
        atomicAdd(&red[D + c0 + c], s2[c]);
    }
    __syncthreads();
    if (tid < 128) {
        atomicAdd(&g_stats[tid],     (double)red[tid]);
        atomicAdd(&g_stats[D + tid], (double)red[D + tid]);
    }
}

__global__ void affine_kernel(const float* __restrict__ g,
                              const float* __restrict__ be,
                              float invN) {
    int c = threadIdx.x;
    double m = g_stats[c] * (double)invN;
    double v = g_stats[D + c] * (double)invN - m * m;
    float scale = g[c] * rsqrtf((float)v + BN_EPS);
    g_aff[c]     = scale;
    g_aff[D + c] = be[c] - scale * (float)m;
    g_stats[c] = 0.0;
    g_stats[D + c] = 0.0;
}

__global__ void final_kernel(const float* __restrict__ Z,
                             float* __restrict__ out, int total4) {
    int i = blockIdx.x * blockDim.x + threadIdx.x;
    if (i >= total4) return;
    int c0 = (i * 4) & (D - 1);
    float4 vv = ((const float4*)Z)[i];
    float4 a = *(const float4*)&g_aff[c0];
    float4 b = *(const float4*)&g_aff[D + c0];
    float4 o;
    o.x = lrelu(fmaf(a.x, vv.x, b.x));
    o.y = lrelu(fmaf(a.y, vv.y, b.y));
    o.z = lrelu(fmaf(a.z, vv.z, b.z));
    o.w = lrelu(fmaf(a.w, vv.w, b.w));
    ((float4*)out)[i] = o;
}

extern "C" void kernel_launch(void* const* d_in, const int* in_sizes, int n_in,
                              void* d_out, int out_size) {
    const float* self_vecs = (const float*)d_in[0];
    const float* neigh     = (const float*)d_in[1];
    const float* W_t       = (const float*)d_in[2];
    const float* a_att     = (const float*)d_in[3];
    const float* eps       = (const float*)d_in[4];
    const float* W1 = (const float*)d_in[5];
    const float* b1 = (const float*)d_in[6];
    const float* g1 = (const float*)d_in[7];
    const float* be1 = (const float*)d_in[8];
    const float* W2 = (const float*)d_in[9];
    const float* b2 = (const float*)d_in[10];
    const float* g2 = (const float*)d_in[11];
    const float* be2 = (const float*)d_in[12];
    const float* W3 = (const float*)d_in[13];
    const float* b3 = (const float*)d_in[14];
    const float* g3 = (const float*)d_in[15];
    const float* be3 = (const float*)d_in[16];
    float* out = (float*)d_out;

    int N = in_sizes[0] / D;
    float invN = 1.f / (float)N;

    float *px, *pzA, *pzB, *pWc, *paff;
    cudaGetSymbolAddress((void**)&px,   g_x);
    cudaGetSymbolAddress((void**)&pzA,  g_zA);
    cudaGetSymbolAddress((void**)&pzB,  g_zB);
    cudaGetSymbolAddress((void**)&pWc,  g_Wc);
    cudaGetSymbolAddress((void**)&paff, g_aff);

    cudaFuncSetAttribute(gemm_kernel,
                         cudaFuncAttributeMaxDynamicSharedMemorySize, 131072);

    prep_kernel<<<D + 1, D>>>(W_t, W1, a_att);

    int ablocks = (N + 3) / 4;
    attn_kernel<<<ablocks, 128>>>(self_vecs, neigh, eps, N);

    int gblocks = (N + 127) / 128;
    int total4  = N * D / 4;

    gemm_kernel<<<gblocks, 512, 131072>>>(px, pWc, b1, nullptr, pzA, N);
    affine_kernel<<<1, D>>>(g1, be1, invN);
    gemm_kernel<<<gblocks, 512, 131072>>>(pzA, W2, b2, paff, pzB, N);
    affine_kernel<<<1, D>>>(g2, be2, invN);
    gemm_kernel<<<gblocks, 512, 131072>>>(pzB, W3, b3, paff, pzA, N);
    affine_kernel<<<1, D>>>(g3, be3, invN);
    final_kernel<<<(total4 + 255) / 256, 256>>>(pzA, out, total4);
}

// round 2
// speedup vs baseline: 1.1499x; 1.1499x over previous
#include <cuda_runtime.h>

#define D 128
#define KNEIGH 25
#define NMAX 50000
#define ALPHA 0.2f
#define BN_EPS 1e-5f

__device__ float  g_x [NMAX * D];
__device__ float  g_zA[NMAX * D];
__device__ float  g_zB[NMAX * D];
__device__ float  g_Wc[D * D];
__device__ float  g_wsn[2 * D];
__device__ double g_stats[2 * D];
__device__ float  g_aff[2 * D];

__device__ __forceinline__ float lrelu(float v) { return v >= 0.f ? v : ALPHA * v; }

__device__ __forceinline__ unsigned f2tf(float f) {
    unsigned u;
    asm("cvt.rna.tf32.f32 %0, %1;" : "=r"(u) : "f"(f));
    return u;
}

__device__ __forceinline__ void mma_tf32(float* c, const unsigned* a, const unsigned* b) {
    asm volatile(
        "mma.sync.aligned.m16n8k8.row.col.f32.tf32.tf32.f32 "
        "{%0,%1,%2,%3}, {%4,%5,%6,%7}, {%8,%9}, {%0,%1,%2,%3};"
        : "+f"(c[0]), "+f"(c[1]), "+f"(c[2]), "+f"(c[3])
        : "r"(a[0]), "r"(a[1]), "r"(a[2]), "r"(a[3]), "r"(b[0]), "r"(b[1]));
}

// ---------------- K0: fold W_t@W1, project attention vectors, zero stats ----
__global__ void prep_kernel(const float* __restrict__ W_t,
                            const float* __restrict__ W1,
                            const float* __restrict__ a_att) {
    if (blockIdx.x < D) {
        __shared__ float wrow[D];
        int d = blockIdx.x, j = threadIdx.x;
        wrow[j] = W_t[d * D + j];
        __syncthreads();
        float s = 0.f;
#pragma unroll 8
        for (int t = 0; t < D; t++) s = fmaf(wrow[t], W1[t * D + j], s);
        g_Wc[d * D + j] = s;
    } else {
        int d = threadIdx.x;
        float s0 = 0.f, s1 = 0.f;
        for (int t = 0; t < D; t++) {
            float w = W_t[d * D + t];
            s0 = fmaf(w, a_att[t], s0);
            s1 = fmaf(w, a_att[D + t], s1);
        }
        g_wsn[d]     = s0;
        g_wsn[D + d] = s1;
        g_stats[d] = 0.0;
        g_stats[D + d] = 0.0;
    }
}

// ---------------- K1: attention (HBM-bound stream, unchanged) ---------------
__global__ void __launch_bounds__(128) attn_kernel(
    const float* __restrict__ self_vecs,
    const float* __restrict__ neigh,
    const float* __restrict__ eps_p,
    int N) {
    int warp = (int)((blockIdx.x * 128u + threadIdx.x) >> 5);
    int lane = threadIdx.x & 31;
    if (warp >= N) return;

    float4 ws = *(const float4*)&g_wsn[lane * 4];
    float4 wn = *(const float4*)&g_wsn[D + lane * 4];
    float4 sv = *(const float4*)&self_vecs[(size_t)warp * D + lane * 4];

    float4 v[KNEIGH];
    const float* np = neigh + (size_t)warp * KNEIGH * D + lane * 4;
#pragma unroll
    for (int k = 0; k < KNEIGH; k++)
        v[k] = *(const float4*)(np + (size_t)k * D);

    float ss = sv.x * ws.x + sv.y * ws.y + sv.z * ws.z + sv.w * ws.w;
#pragma unroll
    for (int o = 16; o > 0; o >>= 1) ss += __shfl_xor_sync(0xffffffffu, ss, o);

    float sc[KNEIGH];
#pragma unroll
    for (int k = 0; k < KNEIGH; k++) {
        float p = v[k].x * wn.x + v[k].y * wn.y + v[k].z * wn.z + v[k].w * wn.w;
#pragma unroll
        for (int o = 16; o > 0; o >>= 1) p += __shfl_xor_sync(0xffffffffu, p, o);
        p += ss;
        sc[k] = lrelu(p);
    }

    float mx = sc[0];
#pragma unroll
    for (int k = 1; k < KNEIGH; k++) mx = fmaxf(mx, sc[k]);
    float sum = 0.f;
#pragma unroll
    for (int k = 0; k < KNEIGH; k++) { sc[k] = __expf(sc[k] - mx); sum += sc[k]; }
    float inv = 1.f / sum;

    float4 acc = make_float4(0.f, 0.f, 0.f, 0.f);
#pragma unroll
    for (int k = 0; k < KNEIGH; k++) {
        float a = sc[k] * inv;
        acc.x = fmaf(a, v[k].x, acc.x);
        acc.y = fmaf(a, v[k].y, acc.y);
        acc.z = fmaf(a, v[k].z, acc.z);
        acc.w = fmaf(a, v[k].w, acc.w);
    }

    float e = 1.f + *eps_p;
    float4 o;
    o.x = fmaf(e, sv.x, acc.x);
    o.y = fmaf(e, sv.y, acc.y);
    o.z = fmaf(e, sv.z, acc.z);
    o.w = fmaf(e, sv.w, acc.w);
    *(float4*)&g_x[(size_t)warp * D + lane * 4] = o;
}

// ---------------- GEMM via tf32 mma.sync ------------------------------------
// Block tile 128x128xK128. 256 threads = 8 warps in 4(M) x 2(N) grid; each warp
// does 32x64 via m16n8k8 fragments. X tile stored tf32-converted, stride 132
// (conflict-free A loads). W tile tf32, stride 128 (broadcast B loads).
// Prologue: optional per-column affine+lrelu (BN of previous layer).
// Epilogue: bias, store, BN sum/sumsq -> shuffle-reduce -> smem -> global dbl.
#define XST 132
__global__ void __launch_bounds__(256) gemm_tc(
    const float* __restrict__ X,
    const float* __restrict__ W,
    const float* __restrict__ bias,
    const float* __restrict__ aff,
    float* __restrict__ Z,
    int N) {
    extern __shared__ float smem[];
    float*    xsm  = smem;                       // [128][XST]
    unsigned* xsmu = (unsigned*)xsm;
    float*    wsm  = smem + 128 * XST;           // [128][128]
    unsigned* wsmu = (unsigned*)wsm;

    int tid = threadIdx.x;
    int n0  = blockIdx.x * 128;

    // load W -> tf32 smem (layout matches row-major [k][n])
#pragma unroll
    for (int i = 0; i < 16; i++) {
        int vi = tid + i * 256;
        float4 w4 = *(const float4*)&W[vi * 4];
        wsmu[vi * 4 + 0] = f2tf(w4.x);
        wsmu[vi * 4 + 1] = f2tf(w4.y);
        wsmu[vi * 4 + 2] = f2tf(w4.z);
        wsmu[vi * 4 + 3] = f2tf(w4.w);
    }

    // load X tile (+prologue) -> tf32 smem
    {
        int row = tid & 127;
        int kb  = (tid >> 7) * 64;
        bool valid = (n0 + row) < N;
#pragma unroll
        for (int i = 0; i < 16; i++) {
            int k0 = kb + i * 4;
            float4 vv = make_float4(0.f, 0.f, 0.f, 0.f);
            if (valid) vv = *(const float4*)&X[(size_t)(n0 + row) * D + k0];
            if (aff) {
                float4 a = *(const float4*)&aff[k0];
                float4 b = *(const float4*)&aff[D + k0];
                vv.x = lrelu(fmaf(a.x, vv.x, b.x));
                vv.y = lrelu(fmaf(a.y, vv.y, b.y));
                vv.z = lrelu(fmaf(a.z, vv.z, b.z));
                vv.w = lrelu(fmaf(a.w, vv.w, b.w));
            }
            unsigned* p = &xsmu[row * XST + k0];
            p[0] = f2tf(vv.x); p[1] = f2tf(vv.y);
            p[2] = f2tf(vv.z); p[3] = f2tf(vv.w);
        }
    }
    __syncthreads();

    int wid = tid >> 5, lane = tid & 31;
    int warp_m = wid >> 1, warp_n = wid & 1;
    int mbase = warp_m * 32, nbase = warp_n * 64;
    int lq = lane >> 2, lr = lane & 3;

    float acc[2][8][4] = {};

#pragma unroll 2
    for (int ks = 0; ks < 16; ks++) {
        int k0 = ks * 8;
        unsigned b[8][2];
#pragma unroll
        for (int nt = 0; nt < 8; nt++) {
            int c = nbase + nt * 8 + lq;
            b[nt][0] = wsmu[(k0 + lr) * 128 + c];
            b[nt][1] = wsmu[(k0 + lr + 4) * 128 + c];
        }
        unsigned a[2][4];
#pragma unroll
        for (int mt = 0; mt < 2; mt++) {
            int r = mbase + mt * 16 + lq;
            a[mt][0] = xsmu[r * XST + k0 + lr];
            a[mt][1] = xsmu[(r + 8) * XST + k0 + lr];
            a[mt][2] = xsmu[r * XST + k0 + lr + 4];
            a[mt][3] = xsmu[(r + 8) * XST + k0 + lr + 4];
        }
#pragma unroll
        for (int mt = 0; mt < 2; mt++)
#pragma unroll
            for (int nt = 0; nt < 8; nt++)
                mma_tf32(acc[mt][nt], a[mt], b[nt]);
    }

    // epilogue: bias, store, per-column stats
    float cs[8][2], cq[8][2];
#pragma unroll
    for (int nt = 0; nt < 8; nt++) {
        cs[nt][0] = cs[nt][1] = 0.f;
        cq[nt][0] = cq[nt][1] = 0.f;
    }

#pragma unroll
    for (int nt = 0; nt < 8; nt++) {
        int c = nbase + nt * 8 + 2 * lr;
        float bx = bias[c], by = bias[c + 1];
#pragma unroll
        for (int mt = 0; mt < 2; mt++) {
            int r0 = n0 + mbase + mt * 16 + lq;
            int r1 = r0 + 8;
            float o0 = acc[mt][nt][0] + bx;
            float o1 = acc[mt][nt][1] + by;
            float o2 = acc[mt][nt][2] + bx;
            float o3 = acc[mt][nt][3] + by;
            if (r0 < N) {
                *(float2*)&Z[(size_t)r0 * D + c] = make_float2(o0, o1);
                cs[nt][0] += o0; cq[nt][0] += o0 * o0;
                cs[nt][1] += o1; cq[nt][1] += o1 * o1;
            }
            if (r1 < N) {
                *(float2*)&Z[(size_t)r1 * D + c] = make_float2(o2, o3);
                cs[nt][0] += o2; cq[nt][0] += o2 * o2;
                cs[nt][1] += o3; cq[nt][1] += o3 * o3;
            }
        }
    }

    __syncthreads();               // all smem reads done -> reuse as red[256]
    float* red = smem;
    if (tid < 256) red[tid] = 0.f;
    __syncthreads();

#pragma unroll
    for (int nt = 0; nt < 8; nt++) {
#pragma unroll
        for (int j = 0; j < 2; j++) {
            float s = cs[nt][j], q = cq[nt][j];
#pragma unroll
            for (int o = 4; o < 32; o <<= 1) {
                s += __shfl_xor_sync(0xffffffffu, s, o);
                q += __shfl_xor_sync(0xffffffffu, q, o);
            }
            if (lq == 0) {
                int c = nbase + nt * 8 + 2 * lr + j;
                atomicAdd(&red[c], s);
                atomicAdd(&red[D + c], q);
            }
        }
    }
    __syncthreads();
    if (tid < 128) {
        atomicAdd(&g_stats[tid],     (double)red[tid]);
        atomicAdd(&g_stats[D + tid], (double)red[D + tid]);
    }
}

// ---------------- stats -> affine, re-zero ----------------------------------
__global__ void affine_kernel(const float* __restrict__ g,
                              const float* __restrict__ be,
                              float invN) {
    int c = threadIdx.x;
    double m = g_stats[c] * (double)invN;
    double v = g_stats[D + c] * (double)invN - m * m;
    float scale = g[c] * rsqrtf((float)v + BN_EPS);
    g_aff[c]     = scale;
    g_aff[D + c] = be[c] - scale * (float)m;
    g_stats[c] = 0.0;
    g_stats[D + c] = 0.0;
}

// ---------------- final: out = lrelu(a*z3 + b) ------------------------------
__global__ void final_kernel(const float* __restrict__ Z,
                             float* __restrict__ out, int total4) {
    int i = blockIdx.x * blockDim.x + threadIdx.x;
    if (i >= total4) return;
    int c0 = (i * 4) & (D - 1);
    float4 vv = ((const float4*)Z)[i];
    float4 a = *(const float4*)&g_aff[c0];
    float4 b = *(const float4*)&g_aff[D + c0];
    float4 o;
    o.x = lrelu(fmaf(a.x, vv.x, b.x));
    o.y = lrelu(fmaf(a.y, vv.y, b.y));
    o.z = lrelu(fmaf(a.z, vv.z, b.z));
    o.w = lrelu(fmaf(a.w, vv.w, b.w));
    ((float4*)out)[i] = o;
}

extern "C" void kernel_launch(void* const* d_in, const int* in_sizes, int n_in,
                              void* d_out, int out_size) {
    const float* self_vecs = (const float*)d_in[0];
    const float* neigh     = (const float*)d_in[1];
    const float* W_t       = (const float*)d_in[2];
    const float* a_att     = (const float*)d_in[3];
    const float* eps       = (const float*)d_in[4];
    const float* W1 = (const float*)d_in[5];
    const float* b1 = (const float*)d_in[6];
    const float* g1 = (const float*)d_in[7];
    const float* be1 = (const float*)d_in[8];
    const float* W2 = (const float*)d_in[9];
    const float* b2 = (const float*)d_in[10];
    const float* g2 = (const float*)d_in[11];
    const float* be2 = (const float*)d_in[12];
    const float* W3 = (const float*)d_in[13];
    const float* b3 = (const float*)d_in[14];
    const float* g3 = (const float*)d_in[15];
    const float* be3 = (const float*)d_in[16];
    float* out = (float*)d_out;

    int N = in_sizes[0] / D;
    float invN = 1.f / (float)N;

    float *px, *pzA, *pzB, *pWc, *paff;
    cudaGetSymbolAddress((void**)&px,   g_x);
    cudaGetSymbolAddress((void**)&pzA,  g_zA);
    cudaGetSymbolAddress((void**)&pzB,  g_zB);
    cudaGetSymbolAddress((void**)&pWc,  g_Wc);
    cudaGetSymbolAddress((void**)&paff, g_aff);

    const int SMEM = (128 * XST + 128 * 128) * 4;   // 133120 bytes
    cudaFuncSetAttribute(gemm_tc,
                         cudaFuncAttributeMaxDynamicSharedMemorySize, SMEM);

    prep_kernel<<<D + 1, D>>>(W_t, W1, a_att);

    int ablocks = (N + 3) / 4;
    attn_kernel<<<ablocks, 128>>>(self_vecs, neigh, eps, N);

    int gblocks = (N + 127) / 128;
    int total4  = N * D / 4;

    gemm_tc<<<gblocks, 256, SMEM>>>(px, pWc, b1, nullptr, pzA, N);
    affine_kernel<<<1, D>>>(g1, be1, invN);
    gemm_tc<<<gblocks, 256, SMEM>>>(pzA, W2, b2, paff, pzB, N);
    affine_kernel<<<1, D>>>(g2, be2, invN);
    gemm_tc<<<gblocks, 256, SMEM>>>(pzB, W3, b3, paff, pzA, N);
    affine_kernel<<<1, D>>>(g3, be3, invN);
    final_kernel<<<(total4 + 255) / 256, 256>>>(pzA, out, total4);
}